// round 2
// baseline (speedup 1.0000x reference)
#include <cuda_runtime.h>
#include <mma.h>
#include <math.h>

using namespace nvcuda;

#define N_NODES 100000
#define N_EDGES 1600000
#define T_STEPS 8
// gate GEMM: K = 20 (x) + 64 (agg) + 64 (h) = 148, padded to 160

// ---------------- device scratch (no allocations allowed) ----------------
__device__ float g_hbuf[2 * N_NODES * 64];
__device__ float g_c[N_NODES * 64];
__device__ float g_agg[N_NODES * 64];
__device__ float g_gnn[N_NODES * 64];
__device__ float g_xT[T_STEPS * 20 * N_NODES];   // [t][j][n]
__device__ float g_W[256 * 160];     // fused, row-permuted gate weights
__device__ float g_bias[256];        // fused, permuted gate bias
__device__ float g_stats[256];       // [0:128) sum, [128:256) sumsq
__device__ float g_scale[128];
__device__ float g_shift[128];
__device__ int   g_deg[N_NODES];
__device__ int   g_offs[N_NODES + 1];
__device__ int   g_cursor[N_NODES];
__device__ int   g_ssrc[N_EDGES];
__device__ float g_h1[N_NODES * 64];
__device__ float g_hidden[N_NODES * 128];
__device__ int   g_is64;

// ---------------- small utility kernels ----------------
__global__ void zero_state() {
    int stride = gridDim.x * blockDim.x;
    int i0 = blockIdx.x * blockDim.x + threadIdx.x;
    for (int k = i0; k < N_NODES * 64; k += stride) {
        g_hbuf[k] = 0.f;
        g_c[k] = 0.f;
        g_agg[k] = 0.f;
    }
    for (int k = i0; k < N_NODES; k += stride) g_deg[k] = 0;
    if (i0 < 256) g_stats[i0] = 0.f;
}

// Detect whether edge_index is int64 (all high words zero) or int32.
__global__ void detect_kernel(const unsigned int* __restrict__ w) {
    __shared__ unsigned int acc;
    if (threadIdx.x == 0) acc = 0u;
    __syncthreads();
    unsigned int v = 0u;
    for (int i = threadIdx.x; i < 2048; i += blockDim.x) v |= w[2 * i + 1];
    atomicOr(&acc, v);
    __syncthreads();
    if (threadIdx.x == 0) g_is64 = (acc == 0u) ? 1 : 0;
}

__device__ __forceinline__ int edge_val(const void* ei, long long idx) {
    if (g_is64) return (int)((const long long*)ei)[idx];
    return ((const int*)ei)[idx];
}

__global__ void hist_kernel(const void* __restrict__ ei) {
    int stride = gridDim.x * blockDim.x;
    for (int e = blockIdx.x * blockDim.x + threadIdx.x; e < N_EDGES; e += stride) {
        int d = edge_val(ei, (long long)N_EDGES + e);
        atomicAdd(&g_deg[d], 1);
    }
}

__global__ void scan_kernel() {
    __shared__ int warpsums[32];
    __shared__ int s_carry;
    int tid = threadIdx.x, lane = tid & 31, wid = tid >> 5;
    if (tid == 0) s_carry = 0;
    __syncthreads();
    for (int base = 0; base < N_NODES; base += 1024) {
        int i = base + tid;
        int v = (i < N_NODES) ? g_deg[i] : 0;
        int x = v;
        #pragma unroll
        for (int off = 1; off < 32; off <<= 1) {
            int y = __shfl_up_sync(0xFFFFFFFFu, x, off);
            if (lane >= off) x += y;
        }
        if (lane == 31) warpsums[wid] = x;
        __syncthreads();
        if (wid == 0) {
            int wv = warpsums[lane];
            #pragma unroll
            for (int off = 1; off < 32; off <<= 1) {
                int y = __shfl_up_sync(0xFFFFFFFFu, wv, off);
                if (lane >= off) wv += y;
            }
            warpsums[lane] = wv;
        }
        __syncthreads();
        int carry = s_carry;
        int woff = (wid == 0) ? 0 : warpsums[wid - 1];
        int excl = x - v + woff + carry;
        if (i < N_NODES) { g_offs[i] = excl; g_cursor[i] = excl; }
        __syncthreads();
        if (tid == 1023) s_carry = carry + warpsums[31];
        __syncthreads();
    }
    if (tid == 0) g_offs[N_NODES] = s_carry;
}

__global__ void scatter_kernel(const void* __restrict__ ei) {
    int stride = gridDim.x * blockDim.x;
    for (int e = blockIdx.x * blockDim.x + threadIdx.x; e < N_EDGES; e += stride) {
        int s = edge_val(ei, e);
        int d = edge_val(ei, (long long)N_EDGES + e);
        int p = atomicAdd(&g_cursor[d], 1);
        g_ssrc[p] = s;
    }
}

// x (N, 30, 8) -> g_xT[t][j][n], coalesced both ways via padded smem tile.
__global__ void __launch_bounds__(256) transpose_x(const float* __restrict__ x) {
    __shared__ float sm[32 * 241];
    int n0 = blockIdx.x * 32;
    for (int i = threadIdx.x; i < 32 * 240; i += 256) {
        int nl = i / 240, off = i - nl * 240;
        sm[nl * 241 + off] = x[(size_t)n0 * 240 + i];
    }
    __syncthreads();
    #pragma unroll
    for (int w = 0; w < 20; w++) {
        int idx = threadIdx.x + w * 256;   // 0..5119
        int nl = idx & 31;
        int p = idx >> 5;                  // 0..159
        int t = p / 20, j = p - t * 20;
        g_xT[((size_t)t * 20 + j) * N_NODES + n0 + nl] = sm[nl * 241 + 80 + j * 8 + t];
    }
}

// Fold GNN projection into gate weights, permute rows to (i,f,g,o) quads.
__global__ void prep_weights(const float* __restrict__ W_ih, const float* __restrict__ W_hh,
                             const float* __restrict__ b_ih, const float* __restrict__ b_hh,
                             const float* __restrict__ W_rel, const float* __restrict__ b_rel,
                             const float* __restrict__ W_root) {
    int rp = blockIdx.x;
    int u = rp >> 2, q = rp & 3;
    int r = q * 64 + u;
    __shared__ float wg[64];
    int tid = threadIdx.x;  // 64 threads
    wg[tid] = W_ih[r * 84 + 20 + tid];
    __syncthreads();
    int c = tid;
    float m1 = 0.f, m2 = 0.f;
    #pragma unroll 8
    for (int j = 0; j < 64; j++) {
        float w = wg[j];
        m1 += w * W_rel[j * 64 + c];
        m2 += w * W_root[j * 64 + c];
    }
    m2 += W_hh[r * 64 + c];
    g_W[rp * 160 + 20 + c] = m1;
    g_W[rp * 160 + 84 + c] = m2;
    if (c < 20) g_W[rp * 160 + c] = W_ih[r * 84 + c];
    if (c < 12) g_W[rp * 160 + 148 + c] = 0.f;
    if (c == 0) {
        float s = b_ih[r] + b_hh[r];
        for (int j = 0; j < 64; j++) s += wg[j] * b_rel[j];
        g_bias[rp] = s;
    }
}

// ---------------- aggregation: warp per dst node ----------------
__global__ void agg_kernel(const float* __restrict__ h) {
    int gw = (blockIdx.x * blockDim.x + threadIdx.x) >> 5;
    int lane = threadIdx.x & 31;
    if (gw >= N_NODES) return;
    int beg = g_offs[gw], end = g_offs[gw + 1];
    float2 acc = make_float2(0.f, 0.f);
    for (int e = beg; e < end; e++) {
        int s = g_ssrc[e];
        float2 v = *reinterpret_cast<const float2*>(h + (size_t)s * 64 + lane * 2);
        acc.x += v.x;
        acc.y += v.y;
    }
    *reinterpret_cast<float2*>(g_agg + (size_t)gw * 64 + lane * 2) = acc;
}

// ---------------- fused tf32 tensor-core gate GEMM + LSTM epilogue ----------------
// gates[N,256] = A[N,160] @ g_W^T ; A = [x_t(20) | agg(64) | h(64) | 0-pad(12)]
// block tile 128 nodes x 128 gate-cols, 8 warps (4 M x 2 N), warp tile 32x64.
__global__ void __launch_bounds__(256)
gate_kernel(const float* __restrict__ xTt, const float* __restrict__ h_in,
            float* __restrict__ h_out) {
    __shared__ __align__(16) float pool[9216];  // As[128][36] | Bs[128][36]; reused as Csm[128][68]
    float* As = pool;
    float* Bs = pool + 128 * 36;
    int tid = threadIdx.x;
    int warp = tid >> 5;
    int mw = warp >> 1;   // 0..3
    int nw = warp & 1;    // 0..1
    int nodes0 = blockIdx.x * 128;
    int col0 = blockIdx.y * 128;

    wmma::fragment<wmma::accumulator, 16, 16, 8, float> acc[2][4];
    #pragma unroll
    for (int mi = 0; mi < 2; mi++)
        #pragma unroll
        for (int nj = 0; nj < 4; nj++) wmma::fill_fragment(acc[mi][nj], 0.f);

    for (int kt = 0; kt < 160; kt += 32) {
        #pragma unroll
        for (int it = 0; it < 16; it++) {
            int idx = tid + it * 256;
            int m = idx >> 5, kk = idx & 31;
            int n = nodes0 + m, gk = kt + kk;
            float v = 0.f;
            if (n < N_NODES) {
                if (gk < 20)       v = xTt[(size_t)gk * N_NODES + n];
                else if (gk < 84)  v = g_agg[(size_t)n * 64 + gk - 20];
                else if (gk < 148) v = h_in[(size_t)n * 64 + gk - 84];
            }
            As[m * 36 + kk] = v;
        }
        #pragma unroll
        for (int it = 0; it < 16; it++) {
            int idx = tid + it * 256;
            int cc = idx >> 5, kk = idx & 31;
            Bs[cc * 36 + kk] = g_W[(col0 + cc) * 160 + kt + kk];
        }
        __syncthreads();
        #pragma unroll
        for (int ks = 0; ks < 4; ks++) {
            wmma::fragment<wmma::matrix_a, 16, 16, 8, wmma::precision::tf32, wmma::row_major> a[2];
            wmma::fragment<wmma::matrix_b, 16, 16, 8, wmma::precision::tf32, wmma::col_major> b[4];
            #pragma unroll
            for (int mi = 0; mi < 2; mi++) {
                wmma::load_matrix_sync(a[mi], As + (mw * 32 + mi * 16) * 36 + ks * 8, 36);
                #pragma unroll
                for (int e = 0; e < a[mi].num_elements; e++)
                    a[mi].x[e] = wmma::__float_to_tf32(a[mi].x[e]);
            }
            #pragma unroll
            for (int nj = 0; nj < 4; nj++) {
                wmma::load_matrix_sync(b[nj], Bs + (nw * 64 + nj * 16) * 36 + ks * 8, 36);
                #pragma unroll
                for (int e = 0; e < b[nj].num_elements; e++)
                    b[nj].x[e] = wmma::__float_to_tf32(b[nj].x[e]);
            }
            #pragma unroll
            for (int mi = 0; mi < 2; mi++)
                #pragma unroll
                for (int nj = 0; nj < 4; nj++)
                    wmma::mma_sync(acc[mi][nj], a[mi], b[nj], acc[mi][nj]);
        }
        __syncthreads();
    }

    // Epilogue in two 64-column halves through smem (reuses pool).
    float* Csm = pool;  // [128][68]
    #pragma unroll
    for (int half = 0; half < 2; half++) {
        #pragma unroll
        for (int mi = 0; mi < 2; mi++)
            #pragma unroll
            for (int jj = 0; jj < 2; jj++) {
                int nj = 2 * half + jj;
                wmma::store_matrix_sync(Csm + (mw * 32 + mi * 16) * 68 + nw * 32 + jj * 16,
                                        acc[mi][nj], 68, wmma::mem_row_major);
            }
        __syncthreads();
        #pragma unroll
        for (int q = 0; q < 8; q++) {
            int idx = tid + q * 256;   // 0..2047 quads
            int r = idx >> 4;
            int qc = idx & 15;
            int csm0 = qc * 4;
            int n = nodes0 + r;
            if (n < N_NODES) {
                int nw2 = csm0 >> 5, rem = csm0 & 31;
                int gcol = col0 + nw2 * 64 + half * 32 + rem;   // aligned quad
                float4 gv = *reinterpret_cast<const float4*>(Csm + r * 68 + csm0);
                float ig = gv.x + g_bias[gcol + 0];
                float fg = gv.y + g_bias[gcol + 1];
                float gg = gv.z + g_bias[gcol + 2];
                float og = gv.w + g_bias[gcol + 3];
                float si = 1.f / (1.f + __expf(-ig));
                float sf = 1.f / (1.f + __expf(-fg));
                float so = 1.f / (1.f + __expf(-og));
                float tg = 2.f / (1.f + __expf(-2.f * gg)) - 1.f;
                int u = gcol >> 2;
                size_t ci = (size_t)n * 64 + u;
                float cn = sf * g_c[ci] + si * tg;
                g_c[ci] = cn;
                float tcn = 2.f / (1.f + __expf(-2.f * cn)) - 1.f;
                h_out[ci] = so * tcn;
            }
        }
        __syncthreads();
    }
}

// ---------------- generic small GEMM: out = act(A @ W^T + bias) ----------------
template <int AMODE, int EPI>
__global__ void __launch_bounds__(256)
gemm64_kernel(const float* __restrict__ A0, const float* __restrict__ A1,
              const float* __restrict__ Wp0, const float* __restrict__ Wp1,
              const float* __restrict__ bias, float* __restrict__ out,
              int K, int OUT) {
    __shared__ __align__(16) float As[16][68];
    __shared__ __align__(16) float Bs[16][68];
    int tid = threadIdx.x;
    int row0 = blockIdx.x * 64;
    int col0 = blockIdx.y * 64;
    int tr = (tid >> 4) * 4;
    int tc = (tid & 15) * 4;
    float acc[4][4];
    #pragma unroll
    for (int i = 0; i < 4; i++)
        #pragma unroll
        for (int j = 0; j < 4; j++) acc[i][j] = 0.f;

    for (int kt = 0; kt < K; kt += 16) {
        #pragma unroll
        for (int it = 0; it < 4; it++) {
            int idx = tid + it * 256;
            int m = idx >> 4, kk = idx & 15;
            int n = row0 + m, gk = kt + kk;
            float v = 0.f;
            if (n < N_NODES) {
                if (AMODE == 0) {
                    v = A0[(size_t)n * K + gk];
                } else {
                    v = (gk < 64) ? A0[(size_t)n * 64 + gk] : A1[(size_t)n * 64 + gk - 64];
                    if (AMODE == 2) v = v * g_scale[gk] + g_shift[gk];
                }
            }
            As[kk][m] = v;
        }
        #pragma unroll
        for (int it = 0; it < 4; it++) {
            int idx = tid + it * 256;
            int cc = idx >> 4, kk = idx & 15;
            int oc = col0 + cc, gk = kt + kk;
            float w;
            if (Wp1) w = (gk < 64) ? Wp0[oc * 64 + gk] : Wp1[oc * 64 + gk - 64];
            else     w = Wp0[oc * K + gk];
            Bs[kk][cc] = w;
        }
        __syncthreads();
        #pragma unroll
        for (int kk = 0; kk < 16; kk++) {
            float4 a = *reinterpret_cast<const float4*>(&As[kk][tr]);
            float4 b = *reinterpret_cast<const float4*>(&Bs[kk][tc]);
            float av[4] = {a.x, a.y, a.z, a.w};
            float bv[4] = {b.x, b.y, b.z, b.w};
            #pragma unroll
            for (int i = 0; i < 4; i++)
                #pragma unroll
                for (int j = 0; j < 4; j++) acc[i][j] += av[i] * bv[j];
        }
        __syncthreads();
    }
    #pragma unroll
    for (int i = 0; i < 4; i++) {
        int n = row0 + tr + i;
        if (n >= N_NODES) continue;
        #pragma unroll
        for (int j = 0; j < 4; j++) {
            int oc = col0 + tc + j;
            float v = acc[i][j] + bias[oc];
            if (EPI == 1) v = fmaxf(v, 0.f);
            out[(size_t)n * OUT + oc] = v;
        }
    }
}

// ---------------- per-feature stats over nodes ----------------
__global__ void stats_kernel(const float* __restrict__ h, const float* __restrict__ gnn) {
    int c = threadIdx.x & 127;
    int grp = threadIdx.x >> 7;  // 0/1
    int r0 = blockIdx.x * 256;
    int rend = min(r0 + 256, N_NODES);
    float s = 0.f, q = 0.f;
    for (int r = r0 + grp; r < rend; r += 2) {
        float v = (c < 64) ? h[(size_t)r * 64 + c] : gnn[(size_t)r * 64 + c - 64];
        s += v;
        q += v * v;
    }
    atomicAdd(&g_stats[c], s);
    atomicAdd(&g_stats[128 + c], q);
}

__global__ void finalize_stats(const float* __restrict__ gamma, const float* __restrict__ beta) {
    int c = threadIdx.x;
    float mean = g_stats[c] / (float)N_NODES;
    float var = g_stats[128 + c] / (float)N_NODES - mean * mean;
    float rstd = rsqrtf(var + 1e-5f);
    float sc = rstd * gamma[c];
    g_scale[c] = sc;
    g_shift[c] = beta[c] - mean * sc;
}

// ---------------- final projection ----------------
__global__ void out_kernel(const float* __restrict__ hidden, const float* __restrict__ Wout,
                           const float* __restrict__ bout, float* __restrict__ out) {
    int gw = (blockIdx.x * blockDim.x + threadIdx.x) >> 5;
    int lane = threadIdx.x & 31;
    if (gw >= N_NODES) return;
    const float* hr = hidden + (size_t)gw * 128;
    float s = hr[lane] * Wout[lane] + hr[lane + 32] * Wout[lane + 32] +
              hr[lane + 64] * Wout[lane + 64] + hr[lane + 96] * Wout[lane + 96];
    #pragma unroll
    for (int off = 16; off; off >>= 1) s += __shfl_down_sync(0xFFFFFFFFu, s, off);
    if (lane == 0) out[gw] = 1.f / (1.f + __expf(-(s + bout[0])));
}

// ---------------- launch ----------------
extern "C" void kernel_launch(void* const* d_in, const int* in_sizes, int n_in,
                              void* d_out, int out_size) {
    const float* x      = (const float*)d_in[0];
    const void*  ei     = d_in[1];
    const float* W_ih   = (const float*)d_in[4];
    const float* W_hh   = (const float*)d_in[5];
    const float* b_ih   = (const float*)d_in[6];
    const float* b_hh   = (const float*)d_in[7];
    const float* W_rel  = (const float*)d_in[8];
    const float* b_rel  = (const float*)d_in[9];
    const float* W_root = (const float*)d_in[10];
    const float* gamma  = (const float*)d_in[11];
    const float* beta   = (const float*)d_in[12];
    const float* W1     = (const float*)d_in[13];
    const float* b1     = (const float*)d_in[14];
    const float* W2     = (const float*)d_in[15];
    const float* b2     = (const float*)d_in[16];
    const float* W_out  = (const float*)d_in[17];
    const float* b_out  = (const float*)d_in[18];

    float *hbuf, *agg, *gnn, *h1, *hidden, *xT;
    cudaGetSymbolAddress((void**)&hbuf, g_hbuf);
    cudaGetSymbolAddress((void**)&agg, g_agg);
    cudaGetSymbolAddress((void**)&gnn, g_gnn);
    cudaGetSymbolAddress((void**)&h1, g_h1);
    cudaGetSymbolAddress((void**)&hidden, g_hidden);
    cudaGetSymbolAddress((void**)&xT, g_xT);

    zero_state<<<1024, 256>>>();
    detect_kernel<<<1, 256>>>((const unsigned int*)ei);
    prep_weights<<<256, 64>>>(W_ih, W_hh, b_ih, b_hh, W_rel, b_rel, W_root);
    transpose_x<<<N_NODES / 32, 256>>>(x);
    hist_kernel<<<512, 256>>>(ei);
    scan_kernel<<<1, 1024>>>();
    scatter_kernel<<<512, 256>>>(ei);

    dim3 ggrid((N_NODES + 127) / 128, 2);
    for (int t = 0; t < T_STEPS; t++) {
        const float* h_in = hbuf + (size_t)(t & 1) * N_NODES * 64;
        float* h_out = hbuf + (size_t)((t + 1) & 1) * N_NODES * 64;
        if (t > 0) agg_kernel<<<(N_NODES * 32 + 255) / 256, 256>>>(h_in);
        if (t == T_STEPS - 1) {
            gemm64_kernel<1, 0><<<dim3((N_NODES + 63) / 64, 1), 256>>>(
                agg, h_in, W_rel, W_root, b_rel, gnn, 128, 64);
        }
        gate_kernel<<<ggrid, 256>>>(xT + (size_t)t * 20 * N_NODES, h_in, h_out);
    }
    const float* hfin = hbuf;  // after 8 steps, state is back in buffer 0

    stats_kernel<<<(N_NODES + 255) / 256, 256>>>(hfin, gnn);
    finalize_stats<<<1, 128>>>(gamma, beta);
    gemm64_kernel<2, 1><<<dim3((N_NODES + 63) / 64, 1), 256>>>(
        hfin, gnn, W1, nullptr, b1, h1, 128, 64);
    gemm64_kernel<0, 1><<<dim3((N_NODES + 63) / 64, 2), 256>>>(
        h1, nullptr, W2, nullptr, b2, hidden, 64, 128);
    out_kernel<<<(N_NODES * 32 + 255) / 256, 256>>>(hidden, W_out, b_out, (float*)d_out);
}

// round 4
// speedup vs baseline: 3.4441x; 3.4441x over previous
#include <cuda_runtime.h>
#include <cuda_bf16.h>
#include <math.h>
#include <cstdint>

#define N_NODES 100000
#define N_EDGES 1600000
#define T_STEPS 8

// ---------------- device scratch (no allocations allowed) ----------------
__device__ float g_hbuf[2 * N_NODES * 64];
__device__ float g_c[N_NODES * 64];
__device__ float g_agg[N_NODES * 64];
__device__ float g_gnn[N_NODES * 64];
__device__ float g_xT[T_STEPS * 20 * N_NODES];   // [t][j][n]
__device__ __align__(16) __nv_bfloat16 g_Wb[256 * 160]; // fused, row-permuted gate weights
__device__ float g_bias[256];
__device__ float g_stats[256];
__device__ float g_scale[128];
__device__ float g_shift[128];
__device__ int   g_deg[N_NODES];
__device__ int   g_offs[N_NODES + 1];
__device__ int   g_cursor[N_NODES];
__device__ int   g_ssrc[N_EDGES];
__device__ float g_h1[N_NODES * 64];
__device__ float g_hidden[N_NODES * 128];
__device__ int   g_is64;

// ---------------- mma/ldmatrix helpers (sm_80+ PTX, safe at compute_103) ---
__device__ __forceinline__ uint32_t smem_u32(const void* p) {
    uint32_t a;
    asm("{ .reg .u64 tmp; cvta.to.shared.u64 tmp, %1; cvt.u32.u64 %0, tmp; }"
        : "=r"(a) : "l"(p));
    return a;
}
__device__ __forceinline__ void ldsm_x4(uint32_t* r, uint32_t addr) {
    asm volatile("ldmatrix.sync.aligned.m8n8.x4.shared.b16 {%0,%1,%2,%3}, [%4];"
                 : "=r"(r[0]), "=r"(r[1]), "=r"(r[2]), "=r"(r[3]) : "r"(addr));
}
__device__ __forceinline__ void mma_bf16(float* d, const uint32_t* a,
                                         uint32_t b0, uint32_t b1) {
    asm volatile(
        "mma.sync.aligned.m16n8k16.row.col.f32.bf16.bf16.f32 "
        "{%0,%1,%2,%3}, {%4,%5,%6,%7}, {%8,%9}, {%0,%1,%2,%3};"
        : "+f"(d[0]), "+f"(d[1]), "+f"(d[2]), "+f"(d[3])
        : "r"(a[0]), "r"(a[1]), "r"(a[2]), "r"(a[3]), "r"(b0), "r"(b1));
}

// ---------------- small utility kernels ----------------
__global__ void zero_state() {
    int stride = gridDim.x * blockDim.x;
    int i0 = blockIdx.x * blockDim.x + threadIdx.x;
    for (int k = i0; k < 2 * N_NODES * 64; k += stride) g_hbuf[k] = 0.f;
    for (int k = i0; k < N_NODES * 64; k += stride) {
        g_c[k] = 0.f;
        g_agg[k] = 0.f;
    }
    for (int k = i0; k < N_NODES; k += stride) g_deg[k] = 0;
    if (i0 < 256) g_stats[i0] = 0.f;
}

__global__ void detect_kernel(const unsigned int* __restrict__ w) {
    __shared__ unsigned int acc;
    if (threadIdx.x == 0) acc = 0u;
    __syncthreads();
    unsigned int v = 0u;
    for (int i = threadIdx.x; i < 2048; i += blockDim.x) v |= w[2 * i + 1];
    atomicOr(&acc, v);
    __syncthreads();
    if (threadIdx.x == 0) g_is64 = (acc == 0u) ? 1 : 0;
}

__device__ __forceinline__ int edge_val(const void* ei, long long idx) {
    if (g_is64) return (int)((const long long*)ei)[idx];
    return ((const int*)ei)[idx];
}

__global__ void hist_kernel(const void* __restrict__ ei) {
    int stride = gridDim.x * blockDim.x;
    for (int e = blockIdx.x * blockDim.x + threadIdx.x; e < N_EDGES; e += stride) {
        int d = edge_val(ei, (long long)N_EDGES + e);
        atomicAdd(&g_deg[d], 1);
    }
}

__global__ void scan_kernel() {
    __shared__ int warpsums[32];
    __shared__ int s_carry;
    int tid = threadIdx.x, lane = tid & 31, wid = tid >> 5;
    if (tid == 0) s_carry = 0;
    __syncthreads();
    for (int base = 0; base < N_NODES; base += 1024) {
        int i = base + tid;
        int v = (i < N_NODES) ? g_deg[i] : 0;
        int x = v;
        #pragma unroll
        for (int off = 1; off < 32; off <<= 1) {
            int y = __shfl_up_sync(0xFFFFFFFFu, x, off);
            if (lane >= off) x += y;
        }
        if (lane == 31) warpsums[wid] = x;
        __syncthreads();
        if (wid == 0) {
            int wv = warpsums[lane];
            #pragma unroll
            for (int off = 1; off < 32; off <<= 1) {
                int y = __shfl_up_sync(0xFFFFFFFFu, wv, off);
                if (lane >= off) wv += y;
            }
            warpsums[lane] = wv;
        }
        __syncthreads();
        int carry = s_carry;
        int woff = (wid == 0) ? 0 : warpsums[wid - 1];
        int excl = x - v + woff + carry;
        if (i < N_NODES) { g_offs[i] = excl; g_cursor[i] = excl; }
        __syncthreads();
        if (tid == 1023) s_carry = carry + warpsums[31];
        __syncthreads();
    }
    if (tid == 0) g_offs[N_NODES] = s_carry;
}

__global__ void scatter_kernel(const void* __restrict__ ei) {
    int stride = gridDim.x * blockDim.x;
    for (int e = blockIdx.x * blockDim.x + threadIdx.x; e < N_EDGES; e += stride) {
        int s = edge_val(ei, e);
        int d = edge_val(ei, (long long)N_EDGES + e);
        int p = atomicAdd(&g_cursor[d], 1);
        g_ssrc[p] = s;
    }
}

// x (N, 30, 8) -> g_xT[t][j][n], coalesced both ways via padded smem tile.
__global__ void __launch_bounds__(256) transpose_x(const float* __restrict__ x) {
    __shared__ float sm[32 * 241];
    int n0 = blockIdx.x * 32;
    for (int i = threadIdx.x; i < 32 * 240; i += 256) {
        int nl = i / 240, off = i - nl * 240;
        sm[nl * 241 + off] = x[(size_t)n0 * 240 + i];
    }
    __syncthreads();
    #pragma unroll
    for (int w = 0; w < 20; w++) {
        int idx = threadIdx.x + w * 256;
        int nl = idx & 31;
        int p = idx >> 5;
        int t = p / 20, j = p - t * 20;
        g_xT[((size_t)t * 20 + j) * N_NODES + n0 + nl] = sm[nl * 241 + 80 + j * 8 + t];
    }
}

// Fold GNN projection into gate weights, permute rows to (i,f,g,o) quads, emit bf16.
__global__ void prep_weights(const float* __restrict__ W_ih, const float* __restrict__ W_hh,
                             const float* __restrict__ b_ih, const float* __restrict__ b_hh,
                             const float* __restrict__ W_rel, const float* __restrict__ b_rel,
                             const float* __restrict__ W_root) {
    int rp = blockIdx.x;
    int u = rp >> 2, q = rp & 3;
    int r = q * 64 + u;
    __shared__ float wg[64];
    int tid = threadIdx.x;  // 64 threads
    wg[tid] = W_ih[r * 84 + 20 + tid];
    __syncthreads();
    int c = tid;
    float m1 = 0.f, m2 = 0.f;
    #pragma unroll 8
    for (int j = 0; j < 64; j++) {
        float w = wg[j];
        m1 += w * W_rel[j * 64 + c];
        m2 += w * W_root[j * 64 + c];
    }
    m2 += W_hh[r * 64 + c];
    g_Wb[rp * 160 + 20 + c] = __float2bfloat16_rn(m1);
    g_Wb[rp * 160 + 84 + c] = __float2bfloat16_rn(m2);
    if (c < 20) g_Wb[rp * 160 + c] = __float2bfloat16_rn(W_ih[r * 84 + c]);
    if (c < 12) g_Wb[rp * 160 + 148 + c] = __float2bfloat16_rn(0.f);
    if (c == 0) {
        float s = b_ih[r] + b_hh[r];
        for (int j = 0; j < 64; j++) s += wg[j] * b_rel[j];
        g_bias[rp] = s;
    }
}

// ---------------- aggregation: warp per dst node ----------------
__global__ void agg_kernel(const float* __restrict__ h) {
    int gw = (blockIdx.x * blockDim.x + threadIdx.x) >> 5;
    int lane = threadIdx.x & 31;
    if (gw >= N_NODES) return;
    int beg = g_offs[gw], end = g_offs[gw + 1];
    float2 acc = make_float2(0.f, 0.f);
    for (int e = beg; e < end; e++) {
        int s = g_ssrc[e];
        float2 v = *reinterpret_cast<const float2*>(h + (size_t)s * 64 + lane * 2);
        acc.x += v.x;
        acc.y += v.y;
    }
    *reinterpret_cast<float2*>(g_agg + (size_t)gw * 64 + lane * 2) = acc;
}

// ---------------- bf16 mma.sync gate GEMM + fused LSTM epilogue ----------------
// gates[128 x 128cols] = A[128 x 160] @ W^T ; A = [x_t(20)|agg(64)|h(64)|0(12)]
// smem: A bf16 [128][168] (stride 336B), B bf16 [128][168]; 8 warps = 4m x 2n,
// warp tile 32x64, mma.m16n8k16. Epilogue pairs lanes via shfl_xor(1) so each
// lane owns a full (i,f,g,o) quad = one hidden unit.
#define GATE_SMEM 86016   // 2 * 128 * 336

__global__ void __launch_bounds__(256, 2)
gate_kernel(const float* __restrict__ xTt, const float* __restrict__ h_in,
            float* __restrict__ h_out) {
    extern __shared__ char smem[];
    const int tid = threadIdx.x;
    const int wid = tid >> 5;
    const int lane = tid & 31;
    const int n0 = blockIdx.x * 128;
    const int col0 = blockIdx.y * 128;   // gate-col base (0 or 128)
    const int ubase = col0 >> 2;         // unit base (0 or 32)

    // ---- stage B (this CTA's 128 weight rows, 160 k) ----
    {
        const uint4* Wb4 = reinterpret_cast<const uint4*>(g_Wb + (size_t)col0 * 160);
        #pragma unroll
        for (int it = 0; it < 10; it++) {
            int idx = tid + it * 256;        // 0..2559 = r*20 + c
            int r = idx / 20;
            int c = idx - r * 20;
            *reinterpret_cast<uint4*>(smem + 43008 + r * 336 + c * 16) = Wb4[idx];
        }
    }
    // ---- stage A: x_t (k 0..19) ----
    #pragma unroll
    for (int it = 0; it < 10; it++) {
        int idx = tid + it * 256;            // j*128 + nl
        int j = idx >> 7;
        int nl = idx & 127;
        int n = n0 + nl;
        float v = (n < N_NODES) ? xTt[(size_t)j * N_NODES + n] : 0.f;
        *reinterpret_cast<__nv_bfloat16*>(smem + nl * 336 + j * 2) = __float2bfloat16_rn(v);
    }
    // ---- A: agg (k 20..83) ----
    #pragma unroll
    for (int it = 0; it < 16; it++) {
        int idx = tid + it * 256;
        int nl = idx >> 5;
        int cp = idx & 31;
        int n = n0 + nl;
        float2 v = (n < N_NODES)
            ? reinterpret_cast<const float2*>(g_agg)[(size_t)n * 32 + cp]
            : make_float2(0.f, 0.f);
        *reinterpret_cast<__nv_bfloat162*>(smem + nl * 336 + 40 + 4 * cp) =
            __float22bfloat162_rn(v);
    }
    // ---- A: h (k 84..147) ----
    #pragma unroll
    for (int it = 0; it < 16; it++) {
        int idx = tid + it * 256;
        int nl = idx >> 5;
        int cp = idx & 31;
        int n = n0 + nl;
        float2 v = (n < N_NODES)
            ? reinterpret_cast<const float2*>(h_in)[(size_t)n * 32 + cp]
            : make_float2(0.f, 0.f);
        *reinterpret_cast<__nv_bfloat162*>(smem + nl * 336 + 168 + 4 * cp) =
            __float22bfloat162_rn(v);
    }
    // ---- A: zero pad (k 148..167 covers pad + stride tail) ----
    #pragma unroll
    for (int it = 0; it < 5; it++) {
        int idx = tid + it * 256;            // 0..1279 = nl*10 + p
        int nl = idx / 10;
        int p = idx - nl * 10;
        *reinterpret_cast<uint32_t*>(smem + nl * 336 + 296 + 4 * p) = 0u;
    }
    __syncthreads();

    // ---- mma mainloop ----
    const int mw = wid >> 1;                 // 0..3
    const int nw = wid & 1;                  // 0..1
    const int mr = mw * 32;
    const int nc = nw * 64;
    const uint32_t sbase = smem_u32(smem);
    uint32_t aAddr = sbase + (mr + (lane & 15)) * 336 + ((lane >> 4) << 4);
    uint32_t bAddr = sbase + 43008u + (nc + (lane & 15)) * 336 + ((lane >> 4) << 4);

    float acc[2][8][4];
    #pragma unroll
    for (int mi = 0; mi < 2; mi++)
        #pragma unroll
        for (int nj = 0; nj < 8; nj++)
            #pragma unroll
            for (int e = 0; e < 4; e++) acc[mi][nj][e] = 0.f;

    #pragma unroll
    for (int ks = 0; ks < 10; ks++) {
        uint32_t a[2][4];
        ldsm_x4(a[0], aAddr + ks * 32);
        ldsm_x4(a[1], aAddr + 16 * 336 + ks * 32);
        uint32_t b[4][4];
        #pragma unroll
        for (int nj = 0; nj < 4; nj++)
            ldsm_x4(b[nj], bAddr + nj * 16 * 336 + ks * 32);
        #pragma unroll
        for (int mi = 0; mi < 2; mi++)
            #pragma unroll
            for (int nj2 = 0; nj2 < 8; nj2++) {
                int nj = nj2 >> 1, hi = nj2 & 1;
                mma_bf16(acc[mi][nj2], a[mi], b[nj][hi], b[nj][hi + 2]);
            }
    }
    __syncthreads();

    // ---- repurpose smem: Cs[128][33], Hs[128][33], bias[128] ----
    float* Cs = reinterpret_cast<float*>(smem);
    float* Hs = Cs + 128 * 33;
    float* sbias = Hs + 128 * 33;
    #pragma unroll
    for (int it = 0; it < 16; it++) {
        int idx = tid + it * 256;
        int rr = idx >> 5;
        int u = idx & 31;
        int n = n0 + rr;
        Cs[rr * 33 + u] = (n < N_NODES) ? g_c[(size_t)n * 64 + ubase + u] : 0.f;
    }
    if (tid < 128) sbias[tid] = g_bias[col0 + tid];
    __syncthreads();

    // ---- fused LSTM epilogue ----
    #pragma unroll
    for (int mi = 0; mi < 2; mi++) {
        int row = mr + mi * 16 + (lane >> 2) + ((lane & 1) << 3);
        #pragma unroll
        for (int nj2 = 0; nj2 < 8; nj2++) {
            float d0 = acc[mi][nj2][0], d1 = acc[mi][nj2][1];
            float d2 = acc[mi][nj2][2], d3 = acc[mi][nj2][3];
            float xd0 = __shfl_xor_sync(0xFFFFFFFFu, d0, 1);
            float xd1 = __shfl_xor_sync(0xFFFFFFFFu, d1, 1);
            float xd2 = __shfl_xor_sync(0xFFFFFFFFu, d2, 1);
            float xd3 = __shfl_xor_sync(0xFFFFFFFFu, d3, 1);
            float ig, fg, gg, og;
            if (lane & 1) { ig = xd2; fg = xd3; gg = d2; og = d3; }
            else          { ig = d0;  fg = d1;  gg = xd0; og = xd1; }
            int qb = nc + nj2 * 8 + ((lane & 2) << 1);   // local col quad base
            ig += sbias[qb];
            fg += sbias[qb + 1];
            gg += sbias[qb + 2];
            og += sbias[qb + 3];
            float si = 1.f / (1.f + __expf(-ig));
            float sf = 1.f / (1.f + __expf(-fg));
            float so = 1.f / (1.f + __expf(-og));
            float tg = 2.f / (1.f + __expf(-2.f * gg)) - 1.f;
            int u = qb >> 2;
            float cold = Cs[row * 33 + u];
            float cn = sf * cold + si * tg;
            Cs[row * 33 + u] = cn;
            float tcn = 2.f / (1.f + __expf(-2.f * cn)) - 1.f;
            Hs[row * 33 + u] = so * tcn;
        }
    }
    __syncthreads();

    // ---- coalesced writeback ----
    #pragma unroll
    for (int it = 0; it < 16; it++) {
        int idx = tid + it * 256;
        int rr = idx >> 5;
        int u = idx & 31;
        int n = n0 + rr;
        if (n < N_NODES) {
            size_t o = (size_t)n * 64 + ubase + u;
            g_c[o] = Cs[rr * 33 + u];
            h_out[o] = Hs[rr * 33 + u];
        }
    }
}

// ---------------- generic small GEMM: out = act(A @ W^T + bias) ----------------
template <int AMODE, int EPI>
__global__ void __launch_bounds__(256)
gemm64_kernel(const float* __restrict__ A0, const float* __restrict__ A1,
              const float* __restrict__ Wp0, const float* __restrict__ Wp1,
              const float* __restrict__ bias, float* __restrict__ out,
              int K, int OUT) {
    __shared__ __align__(16) float As[16][68];
    __shared__ __align__(16) float Bs[16][68];
    int tid = threadIdx.x;
    int row0 = blockIdx.x * 64;
    int col0 = blockIdx.y * 64;
    int tr = (tid >> 4) * 4;
    int tc = (tid & 15) * 4;
    float acc[4][4];
    #pragma unroll
    for (int i = 0; i < 4; i++)
        #pragma unroll
        for (int j = 0; j < 4; j++) acc[i][j] = 0.f;

    for (int kt = 0; kt < K; kt += 16) {
        #pragma unroll
        for (int it = 0; it < 4; it++) {
            int idx = tid + it * 256;
            int m = idx >> 4, kk = idx & 15;
            int n = row0 + m, gk = kt + kk;
            float v = 0.f;
            if (n < N_NODES) {
                if (AMODE == 0) {
                    v = A0[(size_t)n * K + gk];
                } else {
                    v = (gk < 64) ? A0[(size_t)n * 64 + gk] : A1[(size_t)n * 64 + gk - 64];
                    if (AMODE == 2) v = v * g_scale[gk] + g_shift[gk];
                }
            }
            As[kk][m] = v;
        }
        #pragma unroll
        for (int it = 0; it < 4; it++) {
            int idx = tid + it * 256;
            int cc = idx >> 4, kk = idx & 15;
            int oc = col0 + cc, gk = kt + kk;
            float w;
            if (Wp1) w = (gk < 64) ? Wp0[oc * 64 + gk] : Wp1[oc * 64 + gk - 64];
            else     w = Wp0[oc * K + gk];
            Bs[kk][cc] = w;
        }
        __syncthreads();
        #pragma unroll
        for (int kk = 0; kk < 16; kk++) {
            float4 a = *reinterpret_cast<const float4*>(&As[kk][tr]);
            float4 b = *reinterpret_cast<const float4*>(&Bs[kk][tc]);
            float av[4] = {a.x, a.y, a.z, a.w};
            float bv[4] = {b.x, b.y, b.z, b.w};
            #pragma unroll
            for (int i = 0; i < 4; i++)
                #pragma unroll
                for (int j = 0; j < 4; j++) acc[i][j] += av[i] * bv[j];
        }
        __syncthreads();
    }
    #pragma unroll
    for (int i = 0; i < 4; i++) {
        int n = row0 + tr + i;
        if (n >= N_NODES) continue;
        #pragma unroll
        for (int j = 0; j < 4; j++) {
            int oc = col0 + tc + j;
            float v = acc[i][j] + bias[oc];
            if (EPI == 1) v = fmaxf(v, 0.f);
            out[(size_t)n * OUT + oc] = v;
        }
    }
}

// ---------------- per-feature stats over nodes ----------------
__global__ void stats_kernel(const float* __restrict__ h, const float* __restrict__ gnn) {
    int c = threadIdx.x & 127;
    int grp = threadIdx.x >> 7;
    int r0 = blockIdx.x * 256;
    int rend = min(r0 + 256, N_NODES);
    float s = 0.f, q = 0.f;
    for (int r = r0 + grp; r < rend; r += 2) {
        float v = (c < 64) ? h[(size_t)r * 64 + c] : gnn[(size_t)r * 64 + c - 64];
        s += v;
        q += v * v;
    }
    atomicAdd(&g_stats[c], s);
    atomicAdd(&g_stats[128 + c], q);
}

__global__ void finalize_stats(const float* __restrict__ gamma, const float* __restrict__ beta) {
    int c = threadIdx.x;
    float mean = g_stats[c] / (float)N_NODES;
    float var = g_stats[128 + c] / (float)N_NODES - mean * mean;
    float rstd = rsqrtf(var + 1e-5f);
    float sc = rstd * gamma[c];
    g_scale[c] = sc;
    g_shift[c] = beta[c] - mean * sc;
}

// ---------------- final projection ----------------
__global__ void out_kernel(const float* __restrict__ hidden, const float* __restrict__ Wout,
                           const float* __restrict__ bout, float* __restrict__ out) {
    int gw = (blockIdx.x * blockDim.x + threadIdx.x) >> 5;
    int lane = threadIdx.x & 31;
    if (gw >= N_NODES) return;
    const float* hr = hidden + (size_t)gw * 128;
    float s = hr[lane] * Wout[lane] + hr[lane + 32] * Wout[lane + 32] +
              hr[lane + 64] * Wout[lane + 64] + hr[lane + 96] * Wout[lane + 96];
    #pragma unroll
    for (int off = 16; off; off >>= 1) s += __shfl_down_sync(0xFFFFFFFFu, s, off);
    if (lane == 0) out[gw] = 1.f / (1.f + __expf(-(s + bout[0])));
}

// ---------------- launch ----------------
extern "C" void kernel_launch(void* const* d_in, const int* in_sizes, int n_in,
                              void* d_out, int out_size) {
    const float* x      = (const float*)d_in[0];
    const void*  ei     = d_in[1];
    const float* W_ih   = (const float*)d_in[4];
    const float* W_hh   = (const float*)d_in[5];
    const float* b_ih   = (const float*)d_in[6];
    const float* b_hh   = (const float*)d_in[7];
    const float* W_rel  = (const float*)d_in[8];
    const float* b_rel  = (const float*)d_in[9];
    const float* W_root = (const float*)d_in[10];
    const float* gamma  = (const float*)d_in[11];
    const float* beta   = (const float*)d_in[12];
    const float* W1     = (const float*)d_in[13];
    const float* b1     = (const float*)d_in[14];
    const float* W2     = (const float*)d_in[15];
    const float* b2     = (const float*)d_in[16];
    const float* W_out  = (const float*)d_in[17];
    const float* b_out  = (const float*)d_in[18];

    float *hbuf, *agg, *gnn, *h1, *hidden, *xT;
    cudaGetSymbolAddress((void**)&hbuf, g_hbuf);
    cudaGetSymbolAddress((void**)&agg, g_agg);
    cudaGetSymbolAddress((void**)&gnn, g_gnn);
    cudaGetSymbolAddress((void**)&h1, g_h1);
    cudaGetSymbolAddress((void**)&hidden, g_hidden);
    cudaGetSymbolAddress((void**)&xT, g_xT);

    cudaFuncSetAttribute(gate_kernel, cudaFuncAttributeMaxDynamicSharedMemorySize,
                         GATE_SMEM);

    zero_state<<<1024, 256>>>();
    detect_kernel<<<1, 256>>>((const unsigned int*)ei);
    prep_weights<<<256, 64>>>(W_ih, W_hh, b_ih, b_hh, W_rel, b_rel, W_root);
    transpose_x<<<N_NODES / 32, 256>>>(x);
    hist_kernel<<<512, 256>>>(ei);
    scan_kernel<<<1, 1024>>>();
    scatter_kernel<<<512, 256>>>(ei);

    dim3 ggrid((N_NODES + 127) / 128, 2);
    for (int t = 0; t < T_STEPS; t++) {
        const float* h_in = hbuf + (size_t)(t & 1) * N_NODES * 64;
        float* h_out = hbuf + (size_t)((t + 1) & 1) * N_NODES * 64;
        if (t > 0) agg_kernel<<<(N_NODES * 32 + 255) / 256, 256>>>(h_in);
        if (t == T_STEPS - 1) {
            gemm64_kernel<1, 0><<<dim3((N_NODES + 63) / 64, 1), 256>>>(
                agg, h_in, W_rel, W_root, b_rel, gnn, 128, 64);
        }
        gate_kernel<<<ggrid, 256, GATE_SMEM>>>(
            xT + (size_t)t * 20 * N_NODES, h_in, h_out);
    }
    const float* hfin = hbuf;  // after 8 steps, state is back in buffer 0

    stats_kernel<<<(N_NODES + 255) / 256, 256>>>(hfin, gnn);
    finalize_stats<<<1, 128>>>(gamma, beta);
    gemm64_kernel<2, 1><<<dim3((N_NODES + 63) / 64, 1), 256>>>(
        hfin, gnn, W1, nullptr, b1, h1, 128, 64);
    gemm64_kernel<0, 1><<<dim3((N_NODES + 63) / 64, 2), 256>>>(
        h1, nullptr, W2, nullptr, b2, hidden, 64, 128);
    out_kernel<<<(N_NODES * 32 + 255) / 256, 256>>>(hidden, W_out, b_out, (float*)d_out);
}